// round 1
// baseline (speedup 1.0000x reference)
#include <cuda_runtime.h>
#include <math.h>

#define SEQ 4096
#define NC 64
#define BLROWS 8192   // BATCH*SEQ

// ---------------- scratch (static device memory; no allocations) ----------------
static constexpr size_t O_XZ   = 0;
static constexpr size_t O_XC   = O_XZ   + (size_t)BLROWS*4096;
static constexpr size_t O_PROJ = O_XC   + (size_t)BLROWS*2048;
static constexpr size_t O_DEC  = O_PROJ + (size_t)BLROWS*48;
static constexpr size_t O_DTX  = O_DEC  + (size_t)BLROWS*2048;
static constexpr size_t O_YI   = O_DTX  + (size_t)BLROWS*2048;
static constexpr size_t O_Y2   = O_YI   + (size_t)BLROWS*2048;
static constexpr size_t O_YN   = O_Y2   + (size_t)BLROWS*2048;
static constexpr size_t O_ACC  = O_YN   + (size_t)BLROWS*2048;
static constexpr size_t O_ST0  = O_ACC  + (size_t)2*NC*2048*16;
static constexpr size_t SCRATCH_TOT = O_ST0 + (size_t)2*NC*2048*16;

static __device__ float g_scratch[SCRATCH_TOT];

__device__ __forceinline__ float siluf(float v) { return v / (1.f + expf(-v)); }
__device__ __forceinline__ float softplusf(float x) { return x > 20.f ? x : log1pf(expf(x)); }

// ---------------- generic fp32 tiled GEMM: C = A(MxK) @ B(KxN), row-major ------
__global__ void __launch_bounds__(256) gemm128(const float* __restrict__ A,
                                               const float* __restrict__ B,
                                               float* __restrict__ C,
                                               int M, int N, int K)
{
    __shared__ float As[8][128];
    __shared__ float Bs[8][128];
    const int tid = threadIdx.x;
    const int tm = tid >> 4, tn = tid & 15;
    const int m0 = blockIdx.y * 128, n0 = blockIdx.x * 128;
    const int arow = tid >> 1, acol = (tid & 1) * 4;
    const int brow = tid >> 5, bcol = (tid & 31) * 4;

    const float* Ap = A + (size_t)(m0 + arow) * K + acol;
    const float* Bp = B + (size_t)brow * N + n0 + bcol;

    float acc[8][8];
#pragma unroll
    for (int i = 0; i < 8; i++)
#pragma unroll
        for (int j = 0; j < 8; j++) acc[i][j] = 0.f;

    for (int k0 = 0; k0 < K; k0 += 8) {
        float4 av = *(const float4*)(Ap + k0);
        float4 bv = *(const float4*)(Bp + (size_t)k0 * N);
        As[acol + 0][arow] = av.x; As[acol + 1][arow] = av.y;
        As[acol + 2][arow] = av.z; As[acol + 3][arow] = av.w;
        *(float4*)&Bs[brow][bcol] = bv;
        __syncthreads();
#pragma unroll
        for (int k = 0; k < 8; k++) {
            float4 a0 = *(const float4*)&As[k][tm * 8];
            float4 a1 = *(const float4*)&As[k][tm * 8 + 4];
            float4 b0 = *(const float4*)&Bs[k][tn * 8];
            float4 b1 = *(const float4*)&Bs[k][tn * 8 + 4];
            float a[8] = {a0.x, a0.y, a0.z, a0.w, a1.x, a1.y, a1.z, a1.w};
            float b[8] = {b0.x, b0.y, b0.z, b0.w, b1.x, b1.y, b1.z, b1.w};
#pragma unroll
            for (int i = 0; i < 8; i++)
#pragma unroll
                for (int j = 0; j < 8; j++) acc[i][j] = fmaf(a[i], b[j], acc[i][j]);
        }
        __syncthreads();
    }
#pragma unroll
    for (int i = 0; i < 8; i++) {
        float* Cp = C + (size_t)(m0 + tm * 8 + i) * N + n0 + tn * 8;
        *(float4*)Cp       = make_float4(acc[i][0], acc[i][1], acc[i][2], acc[i][3]);
        *(float4*)(Cp + 4) = make_float4(acc[i][4], acc[i][5], acc[i][6], acc[i][7]);
    }
}

// ---------------- conv(d=4) + bias + silu -------------------------------------
__global__ void __launch_bounds__(256) conv_silu(const float* __restrict__ xz,
                                                 const float* __restrict__ cw,
                                                 const float* __restrict__ cb,
                                                 float* __restrict__ xc)
{
    int idx = blockIdx.x * 256 + threadIdx.x;   // over BLROWS*2048
    if (idx >= BLROWS * 2048) return;
    int c = idx & 2047;
    int row = idx >> 11;          // b*SEQ + t
    int t = row & (SEQ - 1);
    int b = row >> 12;
    float acc = cb[c];
#pragma unroll
    for (int j = 0; j < 4; j++) {
        int ts = t + j - 3;
        if (ts >= 0)
            acc = fmaf(cw[c * 4 + j], xz[(size_t)(b * SEQ + ts) * 4096 + c], acc);
    }
    xc[idx] = siluf(acc);
}

// ---------------- proj = xc(8192x2048) @ W_xproj(2048x48) ---------------------
__global__ void __launch_bounds__(256) proj_gemm(const float* __restrict__ Xc,
                                                 const float* __restrict__ W,
                                                 float* __restrict__ P)
{
    __shared__ float Xs[16][128];
    __shared__ float Ws[16][48];
    int tid = threadIdx.x;
    int m0 = blockIdx.x * 128;
    int tr = tid >> 4, tc = tid & 15;
    int xrow = tid >> 1, xcol = (tid & 1) * 8;
    float acc[8][3];
#pragma unroll
    for (int i = 0; i < 8; i++) { acc[i][0] = acc[i][1] = acc[i][2] = 0.f; }

    for (int k0 = 0; k0 < 2048; k0 += 16) {
        float4 v0 = *(const float4*)(Xc + (size_t)(m0 + xrow) * 2048 + k0 + xcol);
        float4 v1 = *(const float4*)(Xc + (size_t)(m0 + xrow) * 2048 + k0 + xcol + 4);
        Xs[xcol + 0][xrow] = v0.x; Xs[xcol + 1][xrow] = v0.y;
        Xs[xcol + 2][xrow] = v0.z; Xs[xcol + 3][xrow] = v0.w;
        Xs[xcol + 4][xrow] = v1.x; Xs[xcol + 5][xrow] = v1.y;
        Xs[xcol + 6][xrow] = v1.z; Xs[xcol + 7][xrow] = v1.w;
        for (int idx = tid; idx < 16 * 48; idx += 256)
            Ws[idx / 48][idx % 48] = W[(size_t)(k0 + idx / 48) * 48 + idx % 48];
        __syncthreads();
#pragma unroll
        for (int k = 0; k < 16; k++) {
            float a[8];
#pragma unroll
            for (int i = 0; i < 8; i++) a[i] = Xs[k][tr * 8 + i];
            float b0 = Ws[k][tc * 3], b1 = Ws[k][tc * 3 + 1], b2 = Ws[k][tc * 3 + 2];
#pragma unroll
            for (int i = 0; i < 8; i++) {
                acc[i][0] = fmaf(a[i], b0, acc[i][0]);
                acc[i][1] = fmaf(a[i], b1, acc[i][1]);
                acc[i][2] = fmaf(a[i], b2, acc[i][2]);
            }
        }
        __syncthreads();
    }
#pragma unroll
    for (int i = 0; i < 8; i++) {
        size_t row = m0 + tr * 8 + i;
        P[row * 48 + tc * 3 + 0] = acc[i][0];
        P[row * 48 + tc * 3 + 1] = acc[i][1];
        P[row * 48 + tc * 3 + 2] = acc[i][2];
    }
}

// ---------------- dt = softplus(proj16 @ W_dt + b_dt); decay; dtx -------------
__global__ void __launch_bounds__(256) dt_dec(const float* __restrict__ proj,
                                              const float* __restrict__ Wdt,
                                              const float* __restrict__ bdt,
                                              const float* __restrict__ Alog,
                                              const float* __restrict__ xc,
                                              float* __restrict__ dec,
                                              float* __restrict__ dtx)
{
    int bc = blockIdx.y;          // b*64 + chunk
    int b = bc >> 6, c = bc & 63;
    int i = blockIdx.x * 256 + threadIdx.x;
    int h = i >> 7;
    float Ah = -expf(Alog[h]);
    float w[16];
#pragma unroll
    for (int k = 0; k < 16; k++) w[k] = Wdt[k * 2048 + i];
    float bias = bdt[i];
    __shared__ float p16[16];
    float cum = 0.f;
    for (int t = 0; t < 64; t++) {
        int row = b * SEQ + c * 64 + t;
        if (threadIdx.x < 16) p16[threadIdx.x] = proj[(size_t)row * 48 + threadIdx.x];
        __syncthreads();
        float draw = bias;
#pragma unroll
        for (int k = 0; k < 16; k++) draw = fmaf(p16[k], w[k], draw);
        float dt = softplusf(draw);
        cum += dt;
        size_t idx = (size_t)row * 2048 + i;
        dec[idx] = expf(Ah * cum);
        dtx[idx] = dt * xc[idx];
        __syncthreads();
    }
}

// ---------------- intra-chunk scan (parallel over chunks) ---------------------
__global__ void __launch_bounds__(128) scan_intra(const float* __restrict__ proj,
                                                  float* __restrict__ dec,   // in: decay, out: cumprod
                                                  const float* __restrict__ dtx,
                                                  float* __restrict__ yi,
                                                  float* __restrict__ accb)
{
    int blk = blockIdx.x;         // b*64*16 + c*16 + h
    int h = blk & 15;
    int bc = blk >> 4;
    int c = bc & 63, b = bc >> 6;
    int d = threadIdx.x;
    __shared__ float Bs[64][16], Cs[64][16];
    for (int idx = d; idx < 1024; idx += 128) {
        int t = idx >> 4, n = idx & 15;
        size_t row = (size_t)(b * SEQ + c * 64 + t) * 48;
        Bs[t][n] = proj[row + 16 + n];
        Cs[t][n] = proj[row + 32 + n];
    }
    __syncthreads();
    float s[16];
#pragma unroll
    for (int n = 0; n < 16; n++) s[n] = 0.f;
    float pr = 1.f;
    int i = h * 128 + d;
    for (int t = 0; t < 64; t++) {
        size_t idx = (size_t)(b * SEQ + c * 64 + t) * 2048 + i;
        float de = dec[idx], co = dtx[idx];
        pr *= de;
        float y = 0.f;
#pragma unroll
        for (int n = 0; n < 16; n++) {
            s[n] = fmaf(s[n], de, co * Bs[t][n]);
            y = fmaf(s[n], Cs[t][n], y);
        }
        yi[idx] = y;
        dec[idx] = pr;            // cumulative decay product for phase 3
    }
    size_t base = ((size_t)(b * 64 + c) * 2048 + i) * 16;
#pragma unroll
    for (int n = 0; n < 16; n++) accb[base + n] = s[n];
}

// ---------------- inter-chunk state propagation (cheap sequential) ------------
__global__ void __launch_bounds__(256) scan_inter(const float* __restrict__ dec,
                                                  const float* __restrict__ accb,
                                                  float* __restrict__ st0)
{
    int tid = blockIdx.x * 256 + threadIdx.x;  // 65536 = 2*2048*16
    int n = tid & 15;
    int i = (tid >> 4) & 2047;
    int b = tid >> 15;
    float s = 0.f;
    for (int c = 0; c < 64; c++) {
        size_t sb = ((size_t)(b * 64 + c) * 2048 + i) * 16 + n;
        st0[sb] = s;
        float P = dec[(size_t)(b * SEQ + c * 64 + 63) * 2048 + i];
        s = fmaf(P, s, accb[sb]);
    }
}

// ---------------- finalize: y += cumdec*(C·s0) + skip; gate with silu(z) ------
__global__ void __launch_bounds__(256) finalize_y(const float* __restrict__ proj,
                                                  const float* __restrict__ dec,  // cumprod
                                                  const float* __restrict__ yi,
                                                  const float* __restrict__ xc,
                                                  const float* __restrict__ xz,
                                                  const float* __restrict__ st0,
                                                  const float* __restrict__ Dskip,
                                                  float* __restrict__ y2)
{
    int bc = blockIdx.y;
    int b = bc >> 6, c = bc & 63;
    int i = blockIdx.x * 256 + threadIdx.x;
    int h = i >> 7;
    __shared__ float Cs[64][16];
    for (int idx = threadIdx.x; idx < 1024; idx += 256) {
        int t = idx >> 4, n = idx & 15;
        Cs[t][n] = proj[(size_t)(b * SEQ + c * 64 + t) * 48 + 32 + n];
    }
    __syncthreads();
    float s0[16];
    size_t sb = ((size_t)(b * 64 + c) * 2048 + i) * 16;
#pragma unroll
    for (int n = 0; n < 16; n += 4) {
        float4 v = *(const float4*)(st0 + sb + n);
        s0[n] = v.x; s0[n + 1] = v.y; s0[n + 2] = v.z; s0[n + 3] = v.w;
    }
    float Dk = Dskip[h];
    for (int t = 0; t < 64; t++) {
        int row = b * SEQ + c * 64 + t;
        size_t idx = (size_t)row * 2048 + i;
        float ydot = 0.f;
#pragma unroll
        for (int n = 0; n < 16; n++) ydot = fmaf(Cs[t][n], s0[n], ydot);
        float y = yi[idx] + dec[idx] * ydot + xc[idx] * Dk;
        float z = xz[(size_t)row * 4096 + 2048 + i];
        y2[idx] = y * siluf(z);
    }
}

// ---------------- row LayerNorm over 2048 -------------------------------------
__global__ void __launch_bounds__(256) layernorm_k(const float* __restrict__ y,
                                                   const float* __restrict__ g,
                                                   const float* __restrict__ be,
                                                   float* __restrict__ out)
{
    int row = blockIdx.x;
    int tid = threadIdx.x;
    const float* yr = y + (size_t)row * 2048;
    float4 a = *(const float4*)(yr + tid * 8);
    float4 b = *(const float4*)(yr + tid * 8 + 4);
    float v[8] = {a.x, a.y, a.z, a.w, b.x, b.y, b.z, b.w};
    float s = 0.f, ss = 0.f;
#pragma unroll
    for (int j = 0; j < 8; j++) { s += v[j]; ss = fmaf(v[j], v[j], ss); }
#pragma unroll
    for (int o = 16; o > 0; o >>= 1) {
        s += __shfl_xor_sync(0xFFFFFFFFu, s, o);
        ss += __shfl_xor_sync(0xFFFFFFFFu, ss, o);
    }
    __shared__ float sm[8], sm2[8], tot[2];
    int wid = tid >> 5, lane = tid & 31;
    if (lane == 0) { sm[wid] = s; sm2[wid] = ss; }
    __syncthreads();
    if (tid == 0) {
        float S = 0.f, SS = 0.f;
        for (int w = 0; w < 8; w++) { S += sm[w]; SS += sm2[w]; }
        tot[0] = S; tot[1] = SS;
    }
    __syncthreads();
    float mean = tot[0] * (1.f / 2048.f);
    float var = tot[1] * (1.f / 2048.f) - mean * mean;
    float rstd = rsqrtf(var + 1e-5f);
#pragma unroll
    for (int j = 0; j < 8; j++) {
        int ii = tid * 8 + j;
        out[(size_t)row * 2048 + ii] = (v[j] - mean) * rstd * g[ii] + be[ii];
    }
}

// ---------------- launch -------------------------------------------------------
extern "C" void kernel_launch(void* const* d_in, const int* in_sizes, int n_in,
                              void* d_out, int out_size)
{
    const float* x      = (const float*)d_in[0];
    const float* W_in   = (const float*)d_in[1];
    const float* conv_w = (const float*)d_in[2];
    const float* conv_b = (const float*)d_in[3];
    const float* W_xp   = (const float*)d_in[4];
    const float* W_dt   = (const float*)d_in[5];
    const float* b_dt   = (const float*)d_in[6];
    const float* A_log  = (const float*)d_in[7];
    const float* D_skip = (const float*)d_in[8];
    const float* W_out  = (const float*)d_in[9];
    const float* ln_g   = (const float*)d_in[10];
    const float* ln_b   = (const float*)d_in[11];

    float* S = nullptr;
    cudaGetSymbolAddress((void**)&S, g_scratch);
    float* xz   = S + O_XZ;
    float* xc   = S + O_XC;
    float* proj = S + O_PROJ;
    float* dec  = S + O_DEC;
    float* dtx  = S + O_DTX;
    float* yi   = S + O_YI;
    float* y2   = S + O_Y2;
    float* yn   = S + O_YN;
    float* accb = S + O_ACC;
    float* st0  = S + O_ST0;

    // 1) xz = x @ W_in   (8192x1024 @ 1024x4096)
    gemm128<<<dim3(4096 / 128, BLROWS / 128), 256>>>(x, W_in, xz, BLROWS, 4096, 1024);
    // 2) conv + silu
    conv_silu<<<(BLROWS * 2048) / 256, 256>>>(xz, conv_w, conv_b, xc);
    // 3) proj
    proj_gemm<<<BLROWS / 128, 256>>>(xc, W_xp, proj);
    // 4) dt / decay / dt*x
    dt_dec<<<dim3(8, 128), 256>>>(proj, W_dt, b_dt, A_log, xc, dec, dtx);
    // 5) intra-chunk scan
    scan_intra<<<2 * NC * 16, 128>>>(proj, dec, dtx, yi, accb);
    // 6) inter-chunk propagation
    scan_inter<<<65536 / 256, 256>>>(dec, accb, st0);
    // 7) finalize + gate
    finalize_y<<<dim3(8, 128), 256>>>(proj, dec, yi, xc, xz, st0, D_skip, y2);
    // 8) layernorm
    layernorm_k<<<BLROWS, 256>>>(y2, ln_g, ln_b, yn);
    // 9) out = yn @ W_out   (8192x2048 @ 2048x1024)
    gemm128<<<dim3(1024 / 128, BLROWS / 128), 256>>>(yn, W_out, (float*)d_out, BLROWS, 1024, 2048);
}

// round 3
// speedup vs baseline: 1.6006x; 1.6006x over previous
#include <cuda_runtime.h>
#include <cuda_bf16.h>
#include <math.h>
#include <stdint.h>

#define SEQ 4096
#define NC 64
#define BLROWS 8192   // BATCH*SEQ

// ================= scratch (static device memory; no allocations) =============
static constexpr size_t O_XZ   = 0;                                  // 8192*4096 f32
static constexpr size_t O_XC   = O_XZ   + (size_t)BLROWS*4096;       // 8192*2048
static constexpr size_t O_PROJ = O_XC   + (size_t)BLROWS*2048;       // 8192*48
static constexpr size_t O_DEC  = O_PROJ + (size_t)BLROWS*48;
static constexpr size_t O_DTX  = O_DEC  + (size_t)BLROWS*2048;
static constexpr size_t O_YI   = O_DTX  + (size_t)BLROWS*2048;
static constexpr size_t O_Y2   = O_YI   + (size_t)BLROWS*2048;
static constexpr size_t O_ACC  = O_Y2   + (size_t)BLROWS*2048;
static constexpr size_t O_ST0  = O_ACC  + (size_t)2*NC*2048*16;
static constexpr size_t O_A2G1 = O_ST0  + (size_t)2*NC*2048*16;      // 8192*3072 bf16
static constexpr size_t O_B2G1 = O_A2G1 + (size_t)BLROWS*3072/2;     // 4096*3072 bf16
static constexpr size_t O_A2G2 = O_B2G1 + (size_t)4096*3072/2;       // 8192*6144 bf16
static constexpr size_t O_B2G2 = O_A2G2 + (size_t)BLROWS*6144/2;     // 1024*6144 bf16
static constexpr size_t SCRATCH_TOT = O_B2G2 + (size_t)1024*6144/2;

static __device__ __align__(1024) float g_scratch[SCRATCH_TOT];

__device__ __forceinline__ float siluf(float v) { return v / (1.f + expf(-v)); }
__device__ __forceinline__ float softplusf(float x) { return x > 20.f ? x : log1pf(expf(x)); }

// ================= cp.async helpers ===========================================
__device__ __forceinline__ uint32_t smem_u32(const void* p) {
    uint32_t a;
    asm("{ .reg .u64 t; cvta.to.shared.u64 t, %1; cvt.u32.u64 %0, t; }" : "=r"(a) : "l"(p));
    return a;
}
__device__ __forceinline__ void cpa16(uint32_t dst, const void* src) {
    asm volatile("cp.async.cg.shared.global [%0], [%1], 16;" :: "r"(dst), "l"(src));
}
#define CPA_COMMIT() asm volatile("cp.async.commit_group;" ::: "memory")
#define CPA_WAIT2()  asm volatile("cp.async.wait_group 2;" ::: "memory")

// mma.sync m16n8k16 bf16 -> f32
__device__ __forceinline__ void mma16816(float* c, uint32_t a0, uint32_t a1, uint32_t a2,
                                         uint32_t a3, uint32_t b0, uint32_t b1) {
    asm volatile(
        "mma.sync.aligned.m16n8k16.row.col.f32.bf16.bf16.f32 "
        "{%0,%1,%2,%3}, {%4,%5,%6,%7}, {%8,%9}, {%0,%1,%2,%3};"
        : "+f"(c[0]), "+f"(c[1]), "+f"(c[2]), "+f"(c[3])
        : "r"(a0), "r"(a1), "r"(a2), "r"(a3), "r"(b0), "r"(b1));
}

// ================= HMMA bf16 GEMM: C[M,Nout] = A2[M,Kp] * B2[Nout,Kp]^T =======
// CTA 128x128, 8 warps (2m x 4n), warp tile 64x32. K-chunk 32, 3-stage cp.async.
// SMEM rows padded to 112B (stride 56 bf16): 16B-aligned + conflict-free LDS.
static constexpr int ROWB   = 112;                 // bytes per padded 32-col bf16 row
static constexpr int OPER_B = 128 * ROWB;          // 14336 per operand tile
static constexpr int STAGEB = 2 * OPER_B;          // 28672
static constexpr int GSMEM  = 3 * STAGEB;          // 86016

__global__ void __launch_bounds__(256, 2) mma_gemm(const __nv_bfloat16* __restrict__ A2,
                                                   const __nv_bfloat16* __restrict__ B2,
                                                   float* __restrict__ C,
                                                   int Kp, int Nout)
{
    extern __shared__ char smem[];
    const uint32_t sb = smem_u32(smem);
    const int tid = threadIdx.x;
    const int w   = tid >> 5;
    const int lane = tid & 31;
    const int wm = w >> 2, wn = w & 3;            // warp grid 2x4
    const int group = lane >> 2, tg = lane & 3;
    const int m0 = blockIdx.y * 128;
    const int n0 = blockIdx.x * 128;

    const int nch = Kp >> 5;                      // chunks of K=32

    // loader: chunk c -> stage s
    auto load_chunk = [&](int c, int s) {
        const int kc = c << 5;
        const uint32_t stA = sb + s * STAGEB;
        const uint32_t stB = stA + OPER_B;
#pragma unroll
        for (int i = 0; i < 2; i++) {
            int t = tid + i * 256;                // 512 x 16B for A
            int row = t >> 2, seg = t & 3;
            cpa16(stA + row * ROWB + seg * 16, A2 + (size_t)(m0 + row) * Kp + kc + seg * 8);
        }
#pragma unroll
        for (int i = 0; i < 2; i++) {
            int t = tid + i * 256;                // 512 x 16B for B
            int row = t >> 2, seg = t & 3;
            cpa16(stB + row * ROWB + seg * 16, B2 + (size_t)(n0 + row) * Kp + kc + seg * 8);
        }
        CPA_COMMIT();
    };

    float acc[4][4][4];
#pragma unroll
    for (int i = 0; i < 4; i++)
#pragma unroll
        for (int j = 0; j < 4; j++)
#pragma unroll
            for (int k = 0; k < 4; k++) acc[i][j][k] = 0.f;

    load_chunk(0, 0); load_chunk(1, 1); load_chunk(2, 2);

    // per-thread SMEM byte bases (within a stage)
    const int aBase = (wm * 64 + group) * ROWB + tg * 4;
    const int bBase = (wn * 32 + group) * ROWB + tg * 4;

    for (int c = 0; c < nch; c++) {
        const int s = c - (c / 3) * 3;
        CPA_WAIT2();
        __syncthreads();
        const char* As = smem + s * STAGEB;
        const char* Bs = As + OPER_B;
#pragma unroll
        for (int ks = 0; ks < 2; ks++) {          // two k16 steps per chunk
            const int ko = ks * 32;               // 16 bf16 = 32B
            uint32_t a[4][4];
#pragma unroll
            for (int mr = 0; mr < 4; mr++) {
                const char* p = As + aBase + mr * 16 * ROWB + ko;
                a[mr][0] = *(const uint32_t*)(p);
                a[mr][1] = *(const uint32_t*)(p + 8 * ROWB);
                a[mr][2] = *(const uint32_t*)(p + 16);
                a[mr][3] = *(const uint32_t*)(p + 8 * ROWB + 16);
            }
            uint32_t b[4][2];
#pragma unroll
            for (int nf = 0; nf < 4; nf++) {
                const char* p = Bs + bBase + nf * 8 * ROWB + ko;
                b[nf][0] = *(const uint32_t*)(p);
                b[nf][1] = *(const uint32_t*)(p + 16);
            }
#pragma unroll
            for (int mr = 0; mr < 4; mr++)
#pragma unroll
                for (int nf = 0; nf < 4; nf++)
                    mma16816(acc[mr][nf], a[mr][0], a[mr][1], a[mr][2], a[mr][3],
                             b[nf][0], b[nf][1]);
        }
        __syncthreads();
        if (c + 3 < nch) load_chunk(c + 3, s);
    }

    // epilogue: direct f32 stores (float2 per fragment row)
#pragma unroll
    for (int mr = 0; mr < 4; mr++) {
        const int r0 = m0 + wm * 64 + mr * 16 + group;
#pragma unroll
        for (int nf = 0; nf < 4; nf++) {
            const int col = n0 + wn * 32 + nf * 8 + tg * 2;
            *(float2*)&C[(size_t)r0 * Nout + col]       = make_float2(acc[mr][nf][0], acc[mr][nf][1]);
            *(float2*)&C[(size_t)(r0 + 8) * Nout + col] = make_float2(acc[mr][nf][2], acc[mr][nf][3]);
        }
    }
}

// ================= split/convert kernels ======================================
// A' = [Ahi | Ahi | Alo] along K (bf16), from fp32 X[M,K]
__global__ void __launch_bounds__(256) asplit(const float* __restrict__ X,
                                              __nv_bfloat16* __restrict__ A2, int K)
{
    int idx = blockIdx.x * 256 + threadIdx.x;
    int m = idx / K, k = idx - m * K;
    float v = X[idx];
    __nv_bfloat16 hi = __float2bfloat16_rn(v);
    __nv_bfloat16 lo = __float2bfloat16_rn(v - __bfloat162float(hi));
    size_t base = (size_t)m * (3 * K);
    A2[base + k] = hi;
    A2[base + K + k] = hi;
    A2[base + 2 * K + k] = lo;
}

// B' = [Bhi | Blo | Bhi] along K, transposed: from fp32 W[K,N] -> B2[N, 3K]
__global__ void __launch_bounds__(256) wsplit_t(const float* __restrict__ W,
                                                __nv_bfloat16* __restrict__ B2,
                                                int K, int N)
{
    __shared__ float t[32][33];
    int k0 = blockIdx.x * 32, n0 = blockIdx.y * 32;
    int tx = threadIdx.x, ty = threadIdx.y;      // 32 x 8
#pragma unroll
    for (int j = 0; j < 32; j += 8)
        t[ty + j][tx] = W[(size_t)(k0 + ty + j) * N + n0 + tx];
    __syncthreads();
#pragma unroll
    for (int j = 0; j < 32; j += 8) {
        int n = n0 + ty + j, k = k0 + tx;
        float v = t[tx][ty + j];
        __nv_bfloat16 hi = __float2bfloat16_rn(v);
        __nv_bfloat16 lo = __float2bfloat16_rn(v - __bfloat162float(hi));
        size_t base = (size_t)n * (3 * K);
        B2[base + k] = hi;
        B2[base + K + k] = lo;
        B2[base + 2 * K + k] = hi;
    }
}

// ================= conv(d=4) + bias + silu ====================================
__global__ void __launch_bounds__(256) conv_silu(const float* __restrict__ xz,
                                                 const float* __restrict__ cw,
                                                 const float* __restrict__ cb,
                                                 float* __restrict__ xc)
{
    int idx = blockIdx.x * 256 + threadIdx.x;
    int c = idx & 2047;
    int row = idx >> 11;
    int t = row & (SEQ - 1);
    int b = row >> 12;
    float acc = cb[c];
#pragma unroll
    for (int j = 0; j < 4; j++) {
        int ts = t + j - 3;
        if (ts >= 0)
            acc = fmaf(cw[c * 4 + j], xz[(size_t)(b * SEQ + ts) * 4096 + c], acc);
    }
    xc[idx] = siluf(acc);
}

// ================= proj = xc(8192x2048) @ W_xproj(2048x48) ====================
__global__ void __launch_bounds__(256) proj_gemm(const float* __restrict__ Xc,
                                                 const float* __restrict__ W,
                                                 float* __restrict__ P)
{
    __shared__ float Xs[16][128];
    __shared__ float Ws[16][48];
    int tid = threadIdx.x;
    int m0 = blockIdx.x * 128;
    int tr = tid >> 4, tc = tid & 15;
    int xrow = tid >> 1, xcol = (tid & 1) * 8;
    float acc[8][3];
#pragma unroll
    for (int i = 0; i < 8; i++) { acc[i][0] = acc[i][1] = acc[i][2] = 0.f; }

    for (int k0 = 0; k0 < 2048; k0 += 16) {
        float4 v0 = *(const float4*)(Xc + (size_t)(m0 + xrow) * 2048 + k0 + xcol);
        float4 v1 = *(const float4*)(Xc + (size_t)(m0 + xrow) * 2048 + k0 + xcol + 4);
        Xs[xcol + 0][xrow] = v0.x; Xs[xcol + 1][xrow] = v0.y;
        Xs[xcol + 2][xrow] = v0.z; Xs[xcol + 3][xrow] = v0.w;
        Xs[xcol + 4][xrow] = v1.x; Xs[xcol + 5][xrow] = v1.y;
        Xs[xcol + 6][xrow] = v1.z; Xs[xcol + 7][xrow] = v1.w;
        for (int idx = tid; idx < 16 * 48; idx += 256)
            Ws[idx / 48][idx % 48] = W[(size_t)(k0 + idx / 48) * 48 + idx % 48];
        __syncthreads();
#pragma unroll
        for (int k = 0; k < 16; k++) {
            float a[8];
#pragma unroll
            for (int i = 0; i < 8; i++) a[i] = Xs[k][tr * 8 + i];
            float b0 = Ws[k][tc * 3], b1 = Ws[k][tc * 3 + 1], b2 = Ws[k][tc * 3 + 2];
#pragma unroll
            for (int i = 0; i < 8; i++) {
                acc[i][0] = fmaf(a[i], b0, acc[i][0]);
                acc[i][1] = fmaf(a[i], b1, acc[i][1]);
                acc[i][2] = fmaf(a[i], b2, acc[i][2]);
            }
        }
        __syncthreads();
    }
#pragma unroll
    for (int i = 0; i < 8; i++) {
        size_t row = m0 + tr * 8 + i;
        P[row * 48 + tc * 3 + 0] = acc[i][0];
        P[row * 48 + tc * 3 + 1] = acc[i][1];
        P[row * 48 + tc * 3 + 2] = acc[i][2];
    }
}

// ================= dt = softplus(proj16 @ W_dt + b_dt); decay; dtx ============
__global__ void __launch_bounds__(256) dt_dec(const float* __restrict__ proj,
                                              const float* __restrict__ Wdt,
                                              const float* __restrict__ bdt,
                                              const float* __restrict__ Alog,
                                              const float* __restrict__ xc,
                                              float* __restrict__ dec,
                                              float* __restrict__ dtx)
{
    int bc = blockIdx.y;          // b*64 + chunk
    int b = bc >> 6, c = bc & 63;
    int i = blockIdx.x * 256 + threadIdx.x;
    int h = i >> 7;
    float Ah = -expf(Alog[h]);
    float w[16];
#pragma unroll
    for (int k = 0; k < 16; k++) w[k] = Wdt[k * 2048 + i];
    float bias = bdt[i];
    __shared__ float p16[64][16];
    int rbase = b * SEQ + c * 64;
    for (int idx = threadIdx.x; idx < 1024; idx += 256) {
        int t = idx >> 4, k = idx & 15;
        p16[t][k] = proj[(size_t)(rbase + t) * 48 + k];
    }
    __syncthreads();
    float cum = 0.f;
    for (int t = 0; t < 64; t++) {
        float draw = bias;
#pragma unroll
        for (int k = 0; k < 16; k++) draw = fmaf(p16[t][k], w[k], draw);
        float dt = softplusf(draw);
        cum += dt;
        size_t idx = (size_t)(rbase + t) * 2048 + i;
        dec[idx] = expf(Ah * cum);
        dtx[idx] = dt * xc[idx];
    }
}

// ================= intra-chunk scan ===========================================
__global__ void __launch_bounds__(128) scan_intra(const float* __restrict__ proj,
                                                  float* __restrict__ dec,
                                                  const float* __restrict__ dtx,
                                                  float* __restrict__ yi,
                                                  float* __restrict__ accb)
{
    int blk = blockIdx.x;
    int h = blk & 15;
    int bc = blk >> 4;
    int c = bc & 63, b = bc >> 6;
    int d = threadIdx.x;
    __shared__ float Bs[64][16], Cs[64][16];
    for (int idx = d; idx < 1024; idx += 128) {
        int t = idx >> 4, n = idx & 15;
        size_t row = (size_t)(b * SEQ + c * 64 + t) * 48;
        Bs[t][n] = proj[row + 16 + n];
        Cs[t][n] = proj[row + 32 + n];
    }
    __syncthreads();
    float s[16];
#pragma unroll
    for (int n = 0; n < 16; n++) s[n] = 0.f;
    float pr = 1.f;
    int i = h * 128 + d;
    for (int t = 0; t < 64; t++) {
        size_t idx = (size_t)(b * SEQ + c * 64 + t) * 2048 + i;
        float de = dec[idx], co = dtx[idx];
        pr *= de;
        float y = 0.f;
#pragma unroll
        for (int n = 0; n < 16; n++) {
            s[n] = fmaf(s[n], de, co * Bs[t][n]);
            y = fmaf(s[n], Cs[t][n], y);
        }
        yi[idx] = y;
        dec[idx] = pr;
    }
    size_t base = ((size_t)(b * 64 + c) * 2048 + i) * 16;
#pragma unroll
    for (int n = 0; n < 16; n++) accb[base + n] = s[n];
}

// ================= inter-chunk state propagation ==============================
__global__ void __launch_bounds__(256) scan_inter(const float* __restrict__ dec,
                                                  const float* __restrict__ accb,
                                                  float* __restrict__ st0)
{
    int tid = blockIdx.x * 256 + threadIdx.x;
    int n = tid & 15;
    int i = (tid >> 4) & 2047;
    int b = tid >> 15;
    float s = 0.f;
    for (int c = 0; c < 64; c++) {
        size_t sb = ((size_t)(b * 64 + c) * 2048 + i) * 16 + n;
        st0[sb] = s;
        float P = dec[(size_t)(b * SEQ + c * 64 + 63) * 2048 + i];
        s = fmaf(P, s, accb[sb]);
    }
}

// ================= finalize: y += cumdec*(C·s0) + skip; gate ==================
__global__ void __launch_bounds__(256) finalize_y(const float* __restrict__ proj,
                                                  const float* __restrict__ dec,
                                                  const float* __restrict__ yi,
                                                  const float* __restrict__ xc,
                                                  const float* __restrict__ xz,
                                                  const float* __restrict__ st0,
                                                  const float* __restrict__ Dskip,
                                                  float* __restrict__ y2)
{
    int bc = blockIdx.y;
    int b = bc >> 6, c = bc & 63;
    int i = blockIdx.x * 256 + threadIdx.x;
    int h = i >> 7;
    __shared__ float Cs[64][16];
    for (int idx = threadIdx.x; idx < 1024; idx += 256) {
        int t = idx >> 4, n = idx & 15;
        Cs[t][n] = proj[(size_t)(b * SEQ + c * 64 + t) * 48 + 32 + n];
    }
    __syncthreads();
    float s0[16];
    size_t sb = ((size_t)(b * 64 + c) * 2048 + i) * 16;
#pragma unroll
    for (int n = 0; n < 16; n += 4) {
        float4 v = *(const float4*)(st0 + sb + n);
        s0[n] = v.x; s0[n + 1] = v.y; s0[n + 2] = v.z; s0[n + 3] = v.w;
    }
    float Dk = Dskip[h];
    for (int t = 0; t < 64; t++) {
        int row = b * SEQ + c * 64 + t;
        size_t idx = (size_t)row * 2048 + i;
        float ydot = 0.f;
#pragma unroll
        for (int n = 0; n < 16; n++) ydot = fmaf(Cs[t][n], s0[n], ydot);
        float y = yi[idx] + dec[idx] * ydot + xc[idx] * Dk;
        float z = xz[(size_t)row * 4096 + 2048 + i];
        y2[idx] = y * siluf(z);
    }
}

// ================= LayerNorm fused with bf16 split output =====================
__global__ void __launch_bounds__(256) layernorm_split(const float* __restrict__ y,
                                                       const float* __restrict__ g,
                                                       const float* __restrict__ be,
                                                       __nv_bfloat16* __restrict__ A2)
{
    int row = blockIdx.x;
    int tid = threadIdx.x;
    const float* yr = y + (size_t)row * 2048;
    float4 a = *(const float4*)(yr + tid * 8);
    float4 b = *(const float4*)(yr + tid * 8 + 4);
    float v[8] = {a.x, a.y, a.z, a.w, b.x, b.y, b.z, b.w};
    float s = 0.f, ss = 0.f;
#pragma unroll
    for (int j = 0; j < 8; j++) { s += v[j]; ss = fmaf(v[j], v[j], ss); }
#pragma unroll
    for (int o = 16; o > 0; o >>= 1) {
        s += __shfl_xor_sync(0xFFFFFFFFu, s, o);
        ss += __shfl_xor_sync(0xFFFFFFFFu, ss, o);
    }
    __shared__ float sm[8], sm2[8], tot[2];
    int wid = tid >> 5, lane = tid & 31;
    if (lane == 0) { sm[wid] = s; sm2[wid] = ss; }
    __syncthreads();
    if (tid == 0) {
        float S = 0.f, SS = 0.f;
        for (int w = 0; w < 8; w++) { S += sm[w]; SS += sm2[w]; }
        tot[0] = S; tot[1] = SS;
    }
    __syncthreads();
    float mean = tot[0] * (1.f / 2048.f);
    float var = tot[1] * (1.f / 2048.f) - mean * mean;
    float rstd = rsqrtf(var + 1e-5f);
    size_t base = (size_t)row * 6144;
#pragma unroll
    for (int j = 0; j < 8; j++) {
        int ii = tid * 8 + j;
        float out = (v[j] - mean) * rstd * g[ii] + be[ii];
        __nv_bfloat16 hi = __float2bfloat16_rn(out);
        __nv_bfloat16 lo = __float2bfloat16_rn(out - __bfloat162float(hi));
        A2[base + ii] = hi;
        A2[base + 2048 + ii] = hi;
        A2[base + 4096 + ii] = lo;
    }
}

// ================= launch ======================================================
extern "C" void kernel_launch(void* const* d_in, const int* in_sizes, int n_in,
                              void* d_out, int out_size)
{
    const float* x      = (const float*)d_in[0];
    const float* W_in   = (const float*)d_in[1];
    const float* conv_w = (const float*)d_in[2];
    const float* conv_b = (const float*)d_in[3];
    const float* W_xp   = (const float*)d_in[4];
    const float* W_dt   = (const float*)d_in[5];
    const float* b_dt   = (const float*)d_in[6];
    const float* A_log  = (const float*)d_in[7];
    const float* D_skip = (const float*)d_in[8];
    const float* W_out  = (const float*)d_in[9];
    const float* ln_g   = (const float*)d_in[10];
    const float* ln_b   = (const float*)d_in[11];

    float* S = nullptr;
    cudaGetSymbolAddress((void**)&S, g_scratch);
    float* xz   = S + O_XZ;
    float* xc   = S + O_XC;
    float* proj = S + O_PROJ;
    float* dec  = S + O_DEC;
    float* dtx  = S + O_DTX;
    float* yi   = S + O_YI;
    float* y2   = S + O_Y2;
    float* accb = S + O_ACC;
    float* st0  = S + O_ST0;
    __nv_bfloat16* A2g1 = (__nv_bfloat16*)(S + O_A2G1);
    __nv_bfloat16* B2g1 = (__nv_bfloat16*)(S + O_B2G1);
    __nv_bfloat16* A2g2 = (__nv_bfloat16*)(S + O_A2G2);
    __nv_bfloat16* B2g2 = (__nv_bfloat16*)(S + O_B2G2);

    cudaFuncSetAttribute(mma_gemm, cudaFuncAttributeMaxDynamicSharedMemorySize, GSMEM);

    // --- operand conversions (weights + x) ---
    asplit<<<(BLROWS * 1024) / 256, 256>>>(x, A2g1, 1024);
    wsplit_t<<<dim3(1024 / 32, 4096 / 32), dim3(32, 8)>>>(W_in, B2g1, 1024, 4096);
    wsplit_t<<<dim3(2048 / 32, 1024 / 32), dim3(32, 8)>>>(W_out, B2g2, 2048, 1024);

    // 1) xz = x @ W_in  via HMMA bf16 split  (Kp=3072, N=4096)
    mma_gemm<<<dim3(4096 / 128, BLROWS / 128), 256, GSMEM>>>(A2g1, B2g1, xz, 3072, 4096);
    // 2) conv + silu
    conv_silu<<<(BLROWS * 2048) / 256, 256>>>(xz, conv_w, conv_b, xc);
    // 3) proj
    proj_gemm<<<BLROWS / 128, 256>>>(xc, W_xp, proj);
    // 4) dt / decay / dt*x
    dt_dec<<<dim3(8, 128), 256>>>(proj, W_dt, b_dt, A_log, xc, dec, dtx);
    // 5) intra-chunk scan
    scan_intra<<<2 * NC * 16, 128>>>(proj, dec, dtx, yi, accb);
    // 6) inter-chunk propagation
    scan_inter<<<65536 / 256, 256>>>(dec, accb, st0);
    // 7) finalize + gate
    finalize_y<<<dim3(8, 128), 256>>>(proj, dec, yi, xc, xz, st0, D_skip, y2);
    // 8) layernorm + bf16 split (A of gemm2)
    layernorm_split<<<BLROWS, 256>>>(y2, ln_g, ln_b, A2g2);
    // 9) out = yn @ W_out  via HMMA bf16 split  (Kp=6144, N=1024)
    mma_gemm<<<dim3(1024 / 128, BLROWS / 128), 256, GSMEM>>>(A2g2, B2g2, (float*)d_out, 6144, 1024);
}